// round 16
// baseline (speedup 1.0000x reference)
#include <cuda_runtime.h>
#include <cuda_fp16.h>
#include <cstdint>

static constexpr int B  = 2;
static constexpr int S  = 2048;
static constexpr int D  = 1024;
static constexpr int NH = 16;
static constexpr int DK = 64;
static constexpr int M  = B * S;   // 4096

// Scratch (allocation-free rule: __device__ globals) — all fp16
__device__ __half g_Qh [M * D];
__device__ __half g_Kh [M * D];
__device__ __half g_Vh [M * D];
__device__ __half g_ATh[M * D];
__device__ __half g_xh [M * D];
__device__ __half g_WQh[D * D];
__device__ __half g_WKh[D * D];
__device__ __half g_WVh[D * D];
__device__ __half g_WOh[D * D];

// ---------------------------------------------------------------------------
// helpers
// ---------------------------------------------------------------------------
__device__ __forceinline__ void mma16(float* c, const uint32_t* a, const uint32_t* b) {
    asm volatile(
        "mma.sync.aligned.m16n8k16.row.col.f32.f16.f16.f32 "
        "{%0,%1,%2,%3}, {%4,%5,%6,%7}, {%8,%9}, {%0,%1,%2,%3};"
        : "+f"(c[0]), "+f"(c[1]), "+f"(c[2]), "+f"(c[3])
        : "r"(a[0]), "r"(a[1]), "r"(a[2]), "r"(a[3]), "r"(b[0]), "r"(b[1]));
}

__device__ __forceinline__ void ldsm_x4(uint32_t& r0, uint32_t& r1,
                                        uint32_t& r2, uint32_t& r3,
                                        uint32_t addr) {
    asm volatile(
        "ldmatrix.sync.aligned.m8n8.x4.shared.b16 {%0,%1,%2,%3}, [%4];"
        : "=r"(r0), "=r"(r1), "=r"(r2), "=r"(r3) : "r"(addr));
}

__device__ __forceinline__ void ldsm_x4_trans(uint32_t& r0, uint32_t& r1,
                                              uint32_t& r2, uint32_t& r3,
                                              uint32_t addr) {
    asm volatile(
        "ldmatrix.sync.aligned.m8n8.x4.trans.shared.b16 {%0,%1,%2,%3}, [%4];"
        : "=r"(r0), "=r"(r1), "=r"(r2), "=r"(r3) : "r"(addr));
}

__device__ __forceinline__ void cp16(uint32_t smem_dst, const void* gsrc) {
    asm volatile("cp.async.cg.shared.global [%0], [%1], 16;"
                 :: "r"(smem_dst), "l"(gsrc));
}
__device__ __forceinline__ void cp_commit() {
    asm volatile("cp.async.commit_group;" ::: "memory");
}
template <int N>
__device__ __forceinline__ void cp_wait() {
    asm volatile("cp.async.wait_group %0;" :: "n"(N) : "memory");
}

__device__ __forceinline__ uint32_t h2u(__half2 h) {
    return *reinterpret_cast<uint32_t*>(&h);
}

// ---------------------------------------------------------------------------
// fp32 -> fp16 input conversion
// ---------------------------------------------------------------------------
__global__ void __launch_bounds__(256)
tohalf_kernel(const float* __restrict__ src, __half* __restrict__ dst, int n4)
{
    int i = blockIdx.x * 256 + threadIdx.x;
    if (i < n4) {
        float4 v = ((const float4*)src)[i];
        uint2 o;
        o.x = h2u(__floats2half2_rn(v.x, v.y));
        o.y = h2u(__floats2half2_rn(v.z, v.w));
        ((uint2*)dst)[i] = o;
    }
}

__global__ void __launch_bounds__(256)
tohalfW_kernel(const float* __restrict__ WQ, const float* __restrict__ WK,
               const float* __restrict__ WV, const float* __restrict__ WO)
{
    int z = blockIdx.y;
    const float* s = (z == 0) ? WQ : (z == 1) ? WK : (z == 2) ? WV : WO;
    __half*      d = (z == 0) ? g_WQh : (z == 1) ? g_WKh : (z == 2) ? g_WVh : g_WOh;
    int i = blockIdx.x * 256 + threadIdx.x;
    float4 v = ((const float4*)s)[i];
    uint2 o;
    o.x = h2u(__floats2half2_rn(v.x, v.y));
    o.y = h2u(__floats2half2_rn(v.z, v.w));
    ((uint2*)d)[i] = o;
}

// ---------------------------------------------------------------------------
// fp16 GEMM: C[m][n] = sum_k A[m][k] * W[n][k]
// 128x128 tile, BK=64 halves, 256 threads = 8 warps (2x4, each 64m x 32n).
// 2-stage cp.async pipeline (one barrier per 64-k slab). Rows 144B ->
// ldsm phases conflict-free. scaleQ folds 1/8*log2(e).
// ---------------------------------------------------------------------------
static constexpr int HKS    = 36;           // uints per row (64 halves + 8 pad)
static constexpr int HSTAGE = 128 * HKS;    // 4608 uints per matrix per stage
static constexpr int GEMM_SMEM_BYTES = 2 * 2 * HSTAGE * 4;   // 73728

static constexpr float QSCALE = 0.125f * 1.44269504088896f;

__device__ __forceinline__ void gemm_h(const __half* __restrict__ A,
                                       const __half* __restrict__ W,
                                       void* __restrict__ Cout, bool halfOut,
                                       const int* __restrict__ pos,
                                       bool doRope, bool scaleQ)
{
    extern __shared__ uint32_t smg[];
    const uint32_t sbase = (uint32_t)__cvta_generic_to_shared(smg);

    const int t    = threadIdx.x;
    const int lane = t & 31;
    const int w    = t >> 5;
    const int g    = lane >> 2;
    const int tq   = lane & 3;
    const int wr   = w >> 2;
    const int wc   = w & 3;
    const int mBase = blockIdx.y * 128;
    const int nBase = blockIdx.x * 128;

    // staging: thread -> row t>>1, half (t&1) of the 128B data row
    const int srow  = t >> 1;
    const int shalf = t & 1;
    const __half* Ag = A + (size_t)(mBase + srow) * D + shalf * 32;
    const __half* Wg = W + (size_t)(nBase + srow) * D + shalf * 32;
    const uint32_t rowOff = (uint32_t)(srow * 144 + shalf * 64);

    // ldmatrix per-lane byte offsets (within a stage)
    const uint32_t aRow = (uint32_t)((wr * 64 + ((lane >> 3) & 1) * 8 + (lane & 7)) * 144
                                     + ((lane >> 4) & 1) * 16);
    const uint32_t bRow = (uint32_t)((wc * 32 + ((lane >> 4) & 1) * 8 + (lane & 7)) * 144
                                     + ((lane >> 3) & 1) * 16);

    float acc[4][4][4];
#pragma unroll
    for (int i = 0; i < 4; i++)
#pragma unroll
        for (int j = 0; j < 4; j++)
#pragma unroll
            for (int r = 0; r < 4; r++) acc[i][j][r] = 0.0f;

    const int NIT = D / 64;   // 16

    {   // prologue: stage 0
        uint32_t ab = sbase + rowOff;
        uint32_t bb = ab + HSTAGE * 4;
#pragma unroll
        for (int j = 0; j < 4; j++) {
            cp16(ab + j * 16, Ag + j * 8);
            cp16(bb + j * 16, Wg + j * 8);
        }
        cp_commit();
    }

    for (int it = 0; it < NIT; it++) {
        cp_wait<0>();
        __syncthreads();

        if (it + 1 < NIT) {   // issue next stage into the other buffer
            uint32_t ab = sbase + (uint32_t)(((it + 1) & 1) * 2 * HSTAGE) * 4 + rowOff;
            uint32_t bb = ab + HSTAGE * 4;
            const __half* Ap = Ag + (it + 1) * 64;
            const __half* Wp = Wg + (it + 1) * 64;
#pragma unroll
            for (int j = 0; j < 4; j++) {
                cp16(ab + j * 16, Ap + j * 8);
                cp16(bb + j * 16, Wp + j * 8);
            }
            cp_commit();
        }

        const uint32_t stA = sbase + (uint32_t)((it & 1) * 2 * HSTAGE) * 4;
        const uint32_t stB = stA + HSTAGE * 4;
#pragma unroll
        for (int kk = 0; kk < 4; kk++) {
            const uint32_t kbB = (uint32_t)(kk * 32);   // bytes
            uint32_t af[4][4], bf[4][2];
#pragma unroll
            for (int mt = 0; mt < 4; mt++)
                ldsm_x4(af[mt][0], af[mt][1], af[mt][2], af[mt][3],
                        stA + aRow + (uint32_t)(mt * 16 * 144) + kbB);
#pragma unroll
            for (int np = 0; np < 2; np++)
                ldsm_x4(bf[np * 2][0], bf[np * 2][1], bf[np * 2 + 1][0],
                        bf[np * 2 + 1][1],
                        stB + bRow + (uint32_t)(np * 16 * 144) + kbB);
#pragma unroll
            for (int mt = 0; mt < 4; mt++)
#pragma unroll
                for (int nt = 0; nt < 4; nt++)
                    mma16(acc[mt][nt], af[mt], bf[nt]);
        }
    }

    const float oscale = scaleQ ? QSCALE : 1.0f;
#pragma unroll
    for (int mt = 0; mt < 4; mt++) {
#pragma unroll
        for (int hi = 0; hi < 2; hi++) {
            int row = mBase + wr * 64 + mt * 16 + g + hi * 8;
            int p   = doRope ? pos[row & (S - 1)] : 0;
#pragma unroll
            for (int nt = 0; nt < 4; nt++) {
                float c0 = acc[mt][nt][hi * 2 + 0];
                float c1 = acc[mt][nt][hi * 2 + 1];
                int col = nBase + wc * 32 + nt * 8 + tq * 2;
                if (doRope) {
                    int e = col & 63;
                    float freq = powf(10000.0f, -(float)e * (1.0f / 64.0f));
                    float sn, cs;
                    sincosf((float)p * freq, &sn, &cs);
                    float v0 = c0, v1 = c1;
                    c0 = cs * v0 - sn * v1;
                    c1 = sn * v0 + cs * v1;
                }
                if (halfOut) {
                    __half* Ch = (__half*)Cout;
                    *(uint32_t*)&Ch[(size_t)row * D + col] =
                        h2u(__floats2half2_rn(c0 * oscale, c1 * oscale));
                } else {
                    float* Cf = (float*)Cout;
                    *(float2*)&Cf[(size_t)row * D + col] = make_float2(c0, c1);
                }
            }
        }
    }
}

__global__ void __launch_bounds__(256)
qkv_kernel(const int* __restrict__ pos)
{
    int z = blockIdx.z;
    const __half* W = (z == 0) ? g_WQh : (z == 1) ? g_WKh : g_WVh;
    __half* Cd      = (z == 0) ? g_Qh  : (z == 1) ? g_Kh  : g_Vh;
    gemm_h(g_xh, W, Cd, true, pos, z < 2, z == 0);
}

__global__ void __launch_bounds__(256)
oproj_kernel(float* __restrict__ out)
{
    gemm_h(g_ATh, g_WOh, out, false, nullptr, false, false);
}

// ---------------------------------------------------------------------------
// Flash attention, fp16 mma. Double-buffered K/V (one barrier per KV tile),
// Q fragments hoisted, P in registers, exp2 softmax, fully-masked-warp skip.
// smem: Q[128][36] | {K,V} x 2 buffers, rows stride 36 uints (144B).
// ---------------------------------------------------------------------------
static constexpr int AQ_OFF  = 0;              // Qs: 128*36 uints
static constexpr int AKV_OFF = 128 * 36;       // KV stage b at AKV_OFF + b*4608
static constexpr int KV_STG  = 2 * 64 * 36;    // 4608 uints (K then V)
static constexpr int ATT_SMEM_BYTES = (AKV_OFF + 2 * KV_STG) * 4;   // 55296

__global__ void __launch_bounds__(256, 2)
attn_kernel()
{
    extern __shared__ uint32_t smu[];
    uint32_t* Qs = smu + AQ_OFF;
    const uint32_t sbase = (uint32_t)__cvta_generic_to_shared(smu);

    const int t    = threadIdx.x;
    const int lane = t & 31;
    const int w    = t >> 5;
    const int g    = lane >> 2;
    const int tq   = lane & 3;
    const int qt   = gridDim.x - 1 - blockIdx.x;   // big tiles first
    const int h    = blockIdx.y;
    const int b    = blockIdx.z;

    // ---- load Q tile (128 x 64 halves, pre-scaled by 1/8*log2e) ----
    {
        const __half* Qg = g_Qh + (size_t)(b * S + qt * 128) * D + h * DK;
        int r  = t >> 1;
        int cb = (t & 1) * 4;
#pragma unroll
        for (int j = 0; j < 4; j++) {
            int ch = cb + j;
            uint4 v = *(const uint4*)(Qg + (size_t)r * D + ch * 8);
            *(uint4*)&Qs[r * 36 + ch * 4] = v;
        }
    }
    __syncthreads();

    // ---- Q fragments: loop-invariant, load once via ldmatrix ----
    uint32_t qfr[4][4];
    {
        const uint32_t qRow = (uint32_t)((w * 16 + ((lane >> 3) & 1) * 8 + (lane & 7)) * 144
                                         + ((lane >> 4) & 1) * 16);
#pragma unroll
        for (int kk = 0; kk < 4; kk++)
            ldsm_x4(qfr[kk][0], qfr[kk][1], qfr[kk][2], qfr[kk][3],
                    sbase + qRow + (uint32_t)(kk * 32));
    }

    float m0 = -1e30f, m1 = -1e30f, l0 = 0.0f, l1 = 0.0f;
    float oacc[8][4];
#pragma unroll
    for (int dt = 0; dt < 8; dt++)
#pragma unroll
        for (int r = 0; r < 4; r++) oacc[dt][r] = 0.0f;

    const __half* Kg = g_Kh + (size_t)(b * S) * D + h * DK;
    const __half* Vg = g_Vh + (size_t)(b * S) * D + h * DK;

    const int nTiles   = 2 * qt + 2;
    const int rowsBase = qt * 128 + w * 16 + g;
    const int warpTop  = qt * 128 + w * 16 + 15;

    const int lr  = t >> 2;
    const int lc0 = (t & 3) * 2;

    const uint32_t kRow = (uint32_t)((((lane >> 4) & 1) * 8 + (lane & 7)) * 144
                                     + ((lane >> 3) & 1) * 16);
    const uint32_t vRow = (uint32_t)(((lane & 7) + ((lane >> 3) & 1) * 8) * 144
                                     + ((lane >> 4) & 1) * 16);

    // ---- prologue: load + store tile 0 into buffer 0 ----
    uint4 kreg[2], vreg[2];
    {
        const __half* Kp = Kg + (size_t)lr * D + lc0 * 8;
        const __half* Vp = Vg + (size_t)lr * D + lc0 * 8;
        kreg[0] = *(const uint4*)(Kp);
        kreg[1] = *(const uint4*)(Kp + 8);
        vreg[0] = *(const uint4*)(Vp);
        vreg[1] = *(const uint4*)(Vp + 8);
    }
    {
        uint32_t* Kb = smu + AKV_OFF;
        uint32_t* Vb = Kb + 64 * 36;
        *(uint4*)&Kb[lr * 36 + lc0 * 4]     = kreg[0];
        *(uint4*)&Kb[lr * 36 + lc0 * 4 + 4] = kreg[1];
        *(uint4*)&Vb[lr * 36 + lc0 * 4]     = vreg[0];
        *(uint4*)&Vb[lr * 36 + lc0 * 4 + 4] = vreg[1];
    }

    for (int tt = 0; tt < nTiles; tt++) {
        // issue next tile's global loads (overlaps this tile's compute)
        if (tt + 1 < nTiles) {
            const __half* Kp = Kg + (size_t)((tt + 1) * 64 + lr) * D + lc0 * 8;
            const __half* Vp = Vg + (size_t)((tt + 1) * 64 + lr) * D + lc0 * 8;
            kreg[0] = *(const uint4*)(Kp);
            kreg[1] = *(const uint4*)(Kp + 8);
            vreg[0] = *(const uint4*)(Vp);
            vreg[1] = *(const uint4*)(Vp + 8);
        }
        __syncthreads();   // tile tt stores visible; buf (tt+1)&1 free
        if (tt + 1 < nTiles) {
            uint32_t* Kb = smu + AKV_OFF + ((tt + 1) & 1) * KV_STG;
            uint32_t* Vb = Kb + 64 * 36;
            *(uint4*)&Kb[lr * 36 + lc0 * 4]     = kreg[0];
            *(uint4*)&Kb[lr * 36 + lc0 * 4 + 4] = kreg[1];
            *(uint4*)&Vb[lr * 36 + lc0 * 4]     = vreg[0];
            *(uint4*)&Vb[lr * 36 + lc0 * 4 + 4] = vreg[1];
        }

        if (warpTop < tt * 64) continue;   // fully masked for this warp

        const uint32_t kbB = sbase + (uint32_t)(AKV_OFF + (tt & 1) * KV_STG) * 4;
        const uint32_t vbB = kbB + 64 * 36 * 4;

        // ---- S = Q K^T  (log2 domain); K fragments via ldmatrix ----
        float sc[8][4];
#pragma unroll
        for (int nt = 0; nt < 8; nt++)
#pragma unroll
            for (int r = 0; r < 4; r++) sc[nt][r] = 0.0f;

#pragma unroll
        for (int kk = 0; kk < 4; kk++) {
            const uint32_t kb = (uint32_t)(kk * 32);
#pragma unroll
            for (int np = 0; np < 4; np++) {
                uint32_t b0, b1, b2, b3;
                ldsm_x4(b0, b1, b2, b3,
                        kbB + kRow + (uint32_t)(np * 16 * 144) + kb);
                uint32_t bA[2] = { b0, b1 };
                uint32_t bB[2] = { b2, b3 };
                mma16(sc[np * 2 + 0], qfr[kk], bA);
                mma16(sc[np * 2 + 1], qfr[kk], bB);
            }
        }

        // ---- causal mask (last two tiles only) ----
        if (tt >= 2 * qt) {
#pragma unroll
            for (int nt = 0; nt < 8; nt++) {
                int col = tt * 64 + nt * 8 + tq * 2;
                if (col > rowsBase)         sc[nt][0] = -1e30f;
                if (col + 1 > rowsBase)     sc[nt][1] = -1e30f;
                if (col > rowsBase + 8)     sc[nt][2] = -1e30f;
                if (col + 1 > rowsBase + 8) sc[nt][3] = -1e30f;
            }
        }

        // ---- online softmax (exp2; rows g, g+8; reduce over 4 lanes) ----
        float mx0 = -1e30f, mx1 = -1e30f;
#pragma unroll
        for (int nt = 0; nt < 8; nt++) {
            mx0 = fmaxf(mx0, fmaxf(sc[nt][0], sc[nt][1]));
            mx1 = fmaxf(mx1, fmaxf(sc[nt][2], sc[nt][3]));
        }
#pragma unroll
        for (int off = 1; off <= 2; off <<= 1) {
            mx0 = fmaxf(mx0, __shfl_xor_sync(0xffffffffu, mx0, off));
            mx1 = fmaxf(mx1, __shfl_xor_sync(0xffffffffu, mx1, off));
        }
        float mn0 = fmaxf(m0, mx0), mn1 = fmaxf(m1, mx1);
        float a0 = exp2f(m0 - mn0), a1 = exp2f(m1 - mn1);
        float rs0 = 0.0f, rs1 = 0.0f;
        uint32_t ph[8][2];   // P in PV A-fragment layout
#pragma unroll
        for (int nt = 0; nt < 8; nt++) {
            float p0 = exp2f(sc[nt][0] - mn0);
            float p1 = exp2f(sc[nt][1] - mn0);
            float p2 = exp2f(sc[nt][2] - mn1);
            float p3 = exp2f(sc[nt][3] - mn1);
            rs0 += p0 + p1;
            rs1 += p2 + p3;
            ph[nt][0] = h2u(__floats2half2_rn(p0, p1));
            ph[nt][1] = h2u(__floats2half2_rn(p2, p3));
        }
#pragma unroll
        for (int off = 1; off <= 2; off <<= 1) {
            rs0 += __shfl_xor_sync(0xffffffffu, rs0, off);
            rs1 += __shfl_xor_sync(0xffffffffu, rs1, off);
        }
        l0 = l0 * a0 + rs0;  m0 = mn0;
        l1 = l1 * a1 + rs1;  m1 = mn1;
#pragma unroll
        for (int dt = 0; dt < 8; dt++) {
            oacc[dt][0] *= a0;  oacc[dt][1] *= a0;
            oacc[dt][2] *= a1;  oacc[dt][3] *= a1;
        }

        // ---- O += P V  (P from regs; V via ldmatrix.x4.trans) ----
#pragma unroll
        for (int kk = 0; kk < 4; kk++) {
            uint32_t pf[4] = { ph[2 * kk][0], ph[2 * kk][1],
                               ph[2 * kk + 1][0], ph[2 * kk + 1][1] };
#pragma unroll
            for (int dt2 = 0; dt2 < 4; dt2++) {
                uint32_t addr = vbB + vRow +
                                (uint32_t)(kk * 16 * 144 + dt2 * 32);
                uint32_t v0, v1, v2, v3;
                ldsm_x4_trans(v0, v1, v2, v3, addr);
                uint32_t bA[2] = { v0, v1 };
                uint32_t bB[2] = { v2, v3 };
                mma16(oacc[dt2 * 2 + 0], pf, bA);
                mma16(oacc[dt2 * 2 + 1], pf, bB);
            }
        }
    }

    // ---- epilogue: normalize, store half to g_ATh ----
    float inv0 = 1.0f / l0, inv1 = 1.0f / l1;
    __half* Og = g_ATh + (size_t)(b * S + qt * 128 + w * 16 + g) * D + h * DK;
#pragma unroll
    for (int dt = 0; dt < 8; dt++) {
        int cc = dt * 8 + tq * 2;
        *(uint32_t*)(Og + cc) =
            h2u(__floats2half2_rn(oacc[dt][0] * inv0, oacc[dt][1] * inv0));
        *(uint32_t*)(Og + 8 * (size_t)D + cc) =
            h2u(__floats2half2_rn(oacc[dt][2] * inv1, oacc[dt][3] * inv1));
    }
}

// ---------------------------------------------------------------------------
extern "C" void kernel_launch(void* const* d_in, const int* in_sizes, int n_in,
                              void* d_out, int out_size)
{
    const float* x   = (const float*)d_in[0];
    const int*   pos = (const int*)  d_in[1];
    const float* WQ  = (const float*)d_in[2];
    const float* WK  = (const float*)d_in[3];
    const float* WV  = (const float*)d_in[4];
    const float* WO  = (const float*)d_in[5];
    float* out = (float*)d_out;

    __half* xh;
    cudaGetSymbolAddress((void**)&xh, g_xh);

    tohalf_kernel<<<(M * D / 4 + 255) / 256, 256>>>(x, xh, M * D / 4);
    tohalfW_kernel<<<dim3(D * D / 4 / 256, 4, 1), 256>>>(WQ, WK, WV, WO);

    cudaFuncSetAttribute(qkv_kernel,
                         cudaFuncAttributeMaxDynamicSharedMemorySize,
                         GEMM_SMEM_BYTES);
    cudaFuncSetAttribute(oproj_kernel,
                         cudaFuncAttributeMaxDynamicSharedMemorySize,
                         GEMM_SMEM_BYTES);
    cudaFuncSetAttribute(attn_kernel,
                         cudaFuncAttributeMaxDynamicSharedMemorySize,
                         ATT_SMEM_BYTES);

    qkv_kernel<<<dim3(D / 128, M / 128, 3), 256, GEMM_SMEM_BYTES>>>(pos);
    attn_kernel<<<dim3(S / 128, NH, B), 256, ATT_SMEM_BYTES>>>();
    oproj_kernel<<<dim3(D / 128, M / 128, 1), 256, GEMM_SMEM_BYTES>>>(out);
}

// round 17
// speedup vs baseline: 1.5558x; 1.5558x over previous
#include <cuda_runtime.h>
#include <cuda_fp16.h>
#include <cstdint>

static constexpr int B  = 2;
static constexpr int S  = 2048;
static constexpr int D  = 1024;
static constexpr int NH = 16;
static constexpr int DK = 64;
static constexpr int M  = B * S;   // 4096

// Scratch (allocation-free rule: __device__ globals) — all fp16
__device__ __half g_Qh [M * D];
__device__ __half g_Kh [M * D];
__device__ __half g_Vh [M * D];
__device__ __half g_ATh[M * D];
__device__ __half g_xh [M * D];
__device__ __half g_WQh[D * D];
__device__ __half g_WKh[D * D];
__device__ __half g_WVh[D * D];
__device__ __half g_WOh[D * D];

// ---------------------------------------------------------------------------
// helpers
// ---------------------------------------------------------------------------
__device__ __forceinline__ void mma16(float* c, const uint32_t* a, const uint32_t* b) {
    asm volatile(
        "mma.sync.aligned.m16n8k16.row.col.f32.f16.f16.f32 "
        "{%0,%1,%2,%3}, {%4,%5,%6,%7}, {%8,%9}, {%0,%1,%2,%3};"
        : "+f"(c[0]), "+f"(c[1]), "+f"(c[2]), "+f"(c[3])
        : "r"(a[0]), "r"(a[1]), "r"(a[2]), "r"(a[3]), "r"(b[0]), "r"(b[1]));
}

__device__ __forceinline__ void ldsm_x4(uint32_t& r0, uint32_t& r1,
                                        uint32_t& r2, uint32_t& r3,
                                        uint32_t addr) {
    asm volatile(
        "ldmatrix.sync.aligned.m8n8.x4.shared.b16 {%0,%1,%2,%3}, [%4];"
        : "=r"(r0), "=r"(r1), "=r"(r2), "=r"(r3) : "r"(addr));
}

__device__ __forceinline__ void ldsm_x4_trans(uint32_t& r0, uint32_t& r1,
                                              uint32_t& r2, uint32_t& r3,
                                              uint32_t addr) {
    asm volatile(
        "ldmatrix.sync.aligned.m8n8.x4.trans.shared.b16 {%0,%1,%2,%3}, [%4];"
        : "=r"(r0), "=r"(r1), "=r"(r2), "=r"(r3) : "r"(addr));
}

__device__ __forceinline__ void cp16(uint32_t smem_dst, const void* gsrc) {
    asm volatile("cp.async.cg.shared.global [%0], [%1], 16;"
                 :: "r"(smem_dst), "l"(gsrc));
}
__device__ __forceinline__ void cp_commit() {
    asm volatile("cp.async.commit_group;" ::: "memory");
}
template <int N>
__device__ __forceinline__ void cp_wait() {
    asm volatile("cp.async.wait_group %0;" :: "n"(N) : "memory");
}

__device__ __forceinline__ uint32_t h2u(__half2 h) {
    return *reinterpret_cast<uint32_t*>(&h);
}

// ---------------------------------------------------------------------------
// fp32 -> fp16 input conversion
// ---------------------------------------------------------------------------
__global__ void __launch_bounds__(256)
tohalf_kernel(const float* __restrict__ src, __half* __restrict__ dst, int n4)
{
    int i = blockIdx.x * 256 + threadIdx.x;
    if (i < n4) {
        float4 v = ((const float4*)src)[i];
        uint2 o;
        o.x = h2u(__floats2half2_rn(v.x, v.y));
        o.y = h2u(__floats2half2_rn(v.z, v.w));
        ((uint2*)dst)[i] = o;
    }
}

__global__ void __launch_bounds__(256)
tohalfW_kernel(const float* __restrict__ WQ, const float* __restrict__ WK,
               const float* __restrict__ WV, const float* __restrict__ WO)
{
    int z = blockIdx.y;
    const float* s = (z == 0) ? WQ : (z == 1) ? WK : (z == 2) ? WV : WO;
    __half*      d = (z == 0) ? g_WQh : (z == 1) ? g_WKh : (z == 2) ? g_WVh : g_WOh;
    int i = blockIdx.x * 256 + threadIdx.x;
    float4 v = ((const float4*)s)[i];
    uint2 o;
    o.x = h2u(__floats2half2_rn(v.x, v.y));
    o.y = h2u(__floats2half2_rn(v.z, v.w));
    ((uint2*)d)[i] = o;
}

// ---------------------------------------------------------------------------
// fp16 GEMM: C[m][n] = sum_k A[m][k] * W[n][k]
// 128x128 tile, BK=32 halves, 256 threads = 8 warps (2x4, each 64m x 32n).
// 3-stage cp.async pipeline; fragments via ldmatrix (rows 80B apart ->
// ldsm phases conflict-free). scaleQ folds 1/8*log2(e).
// ---------------------------------------------------------------------------
static constexpr int HKS    = 20;           // uints per row (80 B)
static constexpr int HSTAGE = 128 * HKS;    // uints per matrix per stage
static constexpr int GEMM_SMEM_BYTES = 3 * 2 * HSTAGE * 4;   // 61440

static constexpr float QSCALE = 0.125f * 1.44269504088896f;

__device__ __forceinline__ void gemm_h(const __half* __restrict__ A,
                                       const __half* __restrict__ W,
                                       void* __restrict__ Cout, bool halfOut,
                                       const int* __restrict__ pos,
                                       bool doRope, bool scaleQ)
{
    extern __shared__ uint32_t smg[];
    const uint32_t sbase = (uint32_t)__cvta_generic_to_shared(smg);

    const int t    = threadIdx.x;
    const int lane = t & 31;
    const int w    = t >> 5;
    const int g    = lane >> 2;
    const int tq   = lane & 3;
    const int wr   = w >> 2;
    const int wc   = w & 3;
    const int mBase = blockIdx.y * 128;
    const int nBase = blockIdx.x * 128;

    const int srow = t >> 1;
    const int sc0  = (t & 1) * 2;
    const __half* Ag = A + (size_t)(mBase + srow) * D + sc0 * 8;
    const __half* Wg = W + (size_t)(nBase + srow) * D + sc0 * 8;
    const uint32_t rowOff = (uint32_t)(srow * HKS * 4 + sc0 * 16);

    // ldmatrix per-lane byte offsets (within a stage)
    const uint32_t aRow = (uint32_t)((wr * 64 + ((lane >> 3) & 1) * 8 + (lane & 7)) * 80
                                     + ((lane >> 4) & 1) * 16);
    const uint32_t bRow = (uint32_t)((wc * 32 + ((lane >> 4) & 1) * 8 + (lane & 7)) * 80
                                     + ((lane >> 3) & 1) * 16);

    float acc[4][4][4];
#pragma unroll
    for (int i = 0; i < 4; i++)
#pragma unroll
        for (int j = 0; j < 4; j++)
#pragma unroll
            for (int r = 0; r < 4; r++) acc[i][j][r] = 0.0f;

    const int NIT = D / 32;

#pragma unroll
    for (int s = 0; s < 2; s++) {
        uint32_t ab = sbase + (uint32_t)(s * 2 * HSTAGE) * 4 + rowOff;
        cp16(ab,      Ag + s * 32);
        cp16(ab + 16, Ag + s * 32 + 8);
        uint32_t bb = ab + HSTAGE * 4;
        cp16(bb,      Wg + s * 32);
        cp16(bb + 16, Wg + s * 32 + 8);
        cp_commit();
    }

    for (int it = 0; it < NIT; it++) {
        cp_wait<1>();
        __syncthreads();

        {
            int s = it + 2;
            if (s < NIT) {
                uint32_t ab = sbase + (uint32_t)((s % 3) * 2 * HSTAGE) * 4 + rowOff;
                cp16(ab,      Ag + s * 32);
                cp16(ab + 16, Ag + s * 32 + 8);
                uint32_t bb = ab + HSTAGE * 4;
                cp16(bb,      Wg + s * 32);
                cp16(bb + 16, Wg + s * 32 + 8);
            }
            cp_commit();
        }

        const uint32_t stA = sbase + (uint32_t)((it % 3) * 2 * HSTAGE) * 4;
        const uint32_t stB = stA + HSTAGE * 4;
#pragma unroll
        for (int kk = 0; kk < 2; kk++) {
            const uint32_t kbB = (uint32_t)(kk * 32);   // bytes
            uint32_t af[4][4], bf[4][2];
#pragma unroll
            for (int mt = 0; mt < 4; mt++)
                ldsm_x4(af[mt][0], af[mt][1], af[mt][2], af[mt][3],
                        stA + aRow + (uint32_t)(mt * 16 * 80) + kbB);
#pragma unroll
            for (int np = 0; np < 2; np++)
                ldsm_x4(bf[np * 2][0], bf[np * 2][1], bf[np * 2 + 1][0],
                        bf[np * 2 + 1][1],
                        stB + bRow + (uint32_t)(np * 16 * 80) + kbB);
#pragma unroll
            for (int mt = 0; mt < 4; mt++)
#pragma unroll
                for (int nt = 0; nt < 4; nt++)
                    mma16(acc[mt][nt], af[mt], bf[nt]);
        }
    }

    const float oscale = scaleQ ? QSCALE : 1.0f;
#pragma unroll
    for (int mt = 0; mt < 4; mt++) {
#pragma unroll
        for (int hi = 0; hi < 2; hi++) {
            int row = mBase + wr * 64 + mt * 16 + g + hi * 8;
            int p   = doRope ? pos[row & (S - 1)] : 0;
#pragma unroll
            for (int nt = 0; nt < 4; nt++) {
                float c0 = acc[mt][nt][hi * 2 + 0];
                float c1 = acc[mt][nt][hi * 2 + 1];
                int col = nBase + wc * 32 + nt * 8 + tq * 2;
                if (doRope) {
                    int e = col & 63;
                    float freq = powf(10000.0f, -(float)e * (1.0f / 64.0f));
                    float sn, cs;
                    sincosf((float)p * freq, &sn, &cs);
                    float v0 = c0, v1 = c1;
                    c0 = cs * v0 - sn * v1;
                    c1 = sn * v0 + cs * v1;
                }
                if (halfOut) {
                    __half* Ch = (__half*)Cout;
                    *(uint32_t*)&Ch[(size_t)row * D + col] =
                        h2u(__floats2half2_rn(c0 * oscale, c1 * oscale));
                } else {
                    float* Cf = (float*)Cout;
                    *(float2*)&Cf[(size_t)row * D + col] = make_float2(c0, c1);
                }
            }
        }
    }
}

__global__ void __launch_bounds__(256)
qkv_kernel(const int* __restrict__ pos)
{
    int z = blockIdx.z;
    const __half* W = (z == 0) ? g_WQh : (z == 1) ? g_WKh : g_WVh;
    __half* Cd      = (z == 0) ? g_Qh  : (z == 1) ? g_Kh  : g_Vh;
    gemm_h(g_xh, W, Cd, true, pos, z < 2, z == 0);
}

__global__ void __launch_bounds__(256)
oproj_kernel(float* __restrict__ out)
{
    gemm_h(g_ATh, g_WOh, out, false, nullptr, false, false);
}

// ---------------------------------------------------------------------------
// Flash attention, fp16 mma. Q fragments hoisted (ldmatrix once), K fragments
// via ldmatrix, P kept in registers, exp2 softmax, masked-warp skip on the
// final diagonal tile. smem rows stride 36 uints.
// ---------------------------------------------------------------------------
static constexpr int AQ_OFF = 0;                  // Qs [128][36]
static constexpr int AK_OFF = 128 * 36;           // Ks [64][36]
static constexpr int AV_OFF = AK_OFF + 64 * 36;   // Vs [64][36]
static constexpr int ATT_SMEM_BYTES = (AV_OFF + 64 * 36) * 4;   // 36864

__global__ void __launch_bounds__(256, 2)
attn_kernel()
{
    extern __shared__ uint32_t smu[];
    uint32_t* Qs = smu + AQ_OFF;
    uint32_t* Ks = smu + AK_OFF;
    uint32_t* Vs = smu + AV_OFF;
    const uint32_t sbase = (uint32_t)__cvta_generic_to_shared(smu);
    const uint32_t kbase = sbase + AK_OFF * 4;
    const uint32_t vbase = sbase + AV_OFF * 4;

    const int t    = threadIdx.x;
    const int lane = t & 31;
    const int w    = t >> 5;
    const int g    = lane >> 2;
    const int tq   = lane & 3;
    const int qt   = gridDim.x - 1 - blockIdx.x;   // big tiles first
    const int h    = blockIdx.y;
    const int b    = blockIdx.z;

    // ---- load Q tile (128 x 64 halves, pre-scaled by 1/8*log2e) ----
    {
        const __half* Qg = g_Qh + (size_t)(b * S + qt * 128) * D + h * DK;
        int r  = t >> 1;
        int cb = (t & 1) * 4;
#pragma unroll
        for (int j = 0; j < 4; j++) {
            int ch = cb + j;
            uint4 v = *(const uint4*)(Qg + (size_t)r * D + ch * 8);
            *(uint4*)&Qs[r * 36 + ch * 4] = v;
        }
    }
    __syncthreads();

    // ---- Q fragments: loop-invariant, load once via ldmatrix ----
    uint32_t qfr[4][4];
    {
        const uint32_t qRow = (uint32_t)((w * 16 + ((lane >> 3) & 1) * 8 + (lane & 7)) * 144
                                         + ((lane >> 4) & 1) * 16);
#pragma unroll
        for (int kk = 0; kk < 4; kk++)
            ldsm_x4(qfr[kk][0], qfr[kk][1], qfr[kk][2], qfr[kk][3],
                    sbase + qRow + (uint32_t)(kk * 32));
    }

    float m0 = -1e30f, m1 = -1e30f, l0 = 0.0f, l1 = 0.0f;
    float oacc[8][4];
#pragma unroll
    for (int dt = 0; dt < 8; dt++)
#pragma unroll
        for (int r = 0; r < 4; r++) oacc[dt][r] = 0.0f;

    const __half* Kg = g_Kh + (size_t)(b * S) * D + h * DK;
    const __half* Vg = g_Vh + (size_t)(b * S) * D + h * DK;

    const int nTiles   = 2 * qt + 2;
    const int rowsBase = qt * 128 + w * 16 + g;
    const int warpTop  = qt * 128 + w * 16 + 15;

    const int lr  = t >> 2;
    const int lc0 = (t & 3) * 2;

    // K ldsm lane offset: [nt-lo,k-lo],[nt-lo,k-hi],[nt-hi,k-lo],[nt-hi,k-hi]
    const uint32_t kRow = (uint32_t)((((lane >> 4) & 1) * 8 + (lane & 7)) * 144
                                     + ((lane >> 3) & 1) * 16);
    // V ldsm.trans lane offset
    const uint32_t vRow = (uint32_t)(((lane & 7) + ((lane >> 3) & 1) * 8) * 144
                                     + ((lane >> 4) & 1) * 16);

    for (int tt = 0; tt < nTiles; tt++) {
        // hoist KV global loads above barrier
        uint4 kreg[2], vreg[2];
        {
            const __half* Kp = Kg + (size_t)(tt * 64 + lr) * D + lc0 * 8;
            const __half* Vp = Vg + (size_t)(tt * 64 + lr) * D + lc0 * 8;
            kreg[0] = *(const uint4*)(Kp);
            kreg[1] = *(const uint4*)(Kp + 8);
            vreg[0] = *(const uint4*)(Vp);
            vreg[1] = *(const uint4*)(Vp + 8);
        }
        __syncthreads();
        *(uint4*)&Ks[lr * 36 + lc0 * 4]     = kreg[0];
        *(uint4*)&Ks[lr * 36 + lc0 * 4 + 4] = kreg[1];
        *(uint4*)&Vs[lr * 36 + lc0 * 4]     = vreg[0];
        *(uint4*)&Vs[lr * 36 + lc0 * 4 + 4] = vreg[1];
        __syncthreads();

        if (warpTop < tt * 64) continue;   // fully masked for this warp

        // ---- S = Q K^T  (log2 domain); K fragments via ldmatrix ----
        float sc[8][4];
#pragma unroll
        for (int nt = 0; nt < 8; nt++)
#pragma unroll
            for (int r = 0; r < 4; r++) sc[nt][r] = 0.0f;

#pragma unroll
        for (int kk = 0; kk < 4; kk++) {
            const uint32_t kb = (uint32_t)(kk * 32);
#pragma unroll
            for (int np = 0; np < 4; np++) {
                uint32_t b0, b1, b2, b3;
                ldsm_x4(b0, b1, b2, b3,
                        kbase + kRow + (uint32_t)(np * 16 * 144) + kb);
                uint32_t bA[2] = { b0, b1 };
                uint32_t bB[2] = { b2, b3 };
                mma16(sc[np * 2 + 0], qfr[kk], bA);
                mma16(sc[np * 2 + 1], qfr[kk], bB);
            }
        }

        // ---- causal mask (last two tiles only) ----
        if (tt >= 2 * qt) {
#pragma unroll
            for (int nt = 0; nt < 8; nt++) {
                int col = tt * 64 + nt * 8 + tq * 2;
                if (col > rowsBase)         sc[nt][0] = -1e30f;
                if (col + 1 > rowsBase)     sc[nt][1] = -1e30f;
                if (col > rowsBase + 8)     sc[nt][2] = -1e30f;
                if (col + 1 > rowsBase + 8) sc[nt][3] = -1e30f;
            }
        }

        // ---- online softmax (exp2; rows g, g+8; reduce over 4 lanes) ----
        float mx0 = -1e30f, mx1 = -1e30f;
#pragma unroll
        for (int nt = 0; nt < 8; nt++) {
            mx0 = fmaxf(mx0, fmaxf(sc[nt][0], sc[nt][1]));
            mx1 = fmaxf(mx1, fmaxf(sc[nt][2], sc[nt][3]));
        }
#pragma unroll
        for (int off = 1; off <= 2; off <<= 1) {
            mx0 = fmaxf(mx0, __shfl_xor_sync(0xffffffffu, mx0, off));
            mx1 = fmaxf(mx1, __shfl_xor_sync(0xffffffffu, mx1, off));
        }
        float mn0 = fmaxf(m0, mx0), mn1 = fmaxf(m1, mx1);
        float a0 = exp2f(m0 - mn0), a1 = exp2f(m1 - mn1);
        float rs0 = 0.0f, rs1 = 0.0f;
        uint32_t ph[8][2];   // P in PV A-fragment layout
#pragma unroll
        for (int nt = 0; nt < 8; nt++) {
            float p0 = exp2f(sc[nt][0] - mn0);
            float p1 = exp2f(sc[nt][1] - mn0);
            float p2 = exp2f(sc[nt][2] - mn1);
            float p3 = exp2f(sc[nt][3] - mn1);
            rs0 += p0 + p1;
            rs1 += p2 + p3;
            ph[nt][0] = h2u(__floats2half2_rn(p0, p1));
            ph[nt][1] = h2u(__floats2half2_rn(p2, p3));
        }
#pragma unroll
        for (int off = 1; off <= 2; off <<= 1) {
            rs0 += __shfl_xor_sync(0xffffffffu, rs0, off);
            rs1 += __shfl_xor_sync(0xffffffffu, rs1, off);
        }
        l0 = l0 * a0 + rs0;  m0 = mn0;
        l1 = l1 * a1 + rs1;  m1 = mn1;
#pragma unroll
        for (int dt = 0; dt < 8; dt++) {
            oacc[dt][0] *= a0;  oacc[dt][1] *= a0;
            oacc[dt][2] *= a1;  oacc[dt][3] *= a1;
        }

        // ---- O += P V  (P from regs; V via ldmatrix.x4.trans) ----
#pragma unroll
        for (int kk = 0; kk < 4; kk++) {
            uint32_t pf[4] = { ph[2 * kk][0], ph[2 * kk][1],
                               ph[2 * kk + 1][0], ph[2 * kk + 1][1] };
#pragma unroll
            for (int dt2 = 0; dt2 < 4; dt2++) {
                uint32_t addr = vbase + vRow +
                                (uint32_t)(kk * 16 * 144 + dt2 * 32);
                uint32_t v0, v1, v2, v3;
                ldsm_x4_trans(v0, v1, v2, v3, addr);
                uint32_t bA[2] = { v0, v1 };
                uint32_t bB[2] = { v2, v3 };
                mma16(oacc[dt2 * 2 + 0], pf, bA);
                mma16(oacc[dt2 * 2 + 1], pf, bB);
            }
        }
    }

    // ---- epilogue: normalize, store half to g_ATh ----
    float inv0 = 1.0f / l0, inv1 = 1.0f / l1;
    __half* Og = g_ATh + (size_t)(b * S + qt * 128 + w * 16 + g) * D + h * DK;
#pragma unroll
    for (int dt = 0; dt < 8; dt++) {
        int cc = dt * 8 + tq * 2;
        *(uint32_t*)(Og + cc) =
            h2u(__floats2half2_rn(oacc[dt][0] * inv0, oacc[dt][1] * inv0));
        *(uint32_t*)(Og + 8 * (size_t)D + cc) =
            h2u(__floats2half2_rn(oacc[dt][2] * inv1, oacc[dt][3] * inv1));
    }
}

// ---------------------------------------------------------------------------
extern "C" void kernel_launch(void* const* d_in, const int* in_sizes, int n_in,
                              void* d_out, int out_size)
{
    const float* x   = (const float*)d_in[0];
    const int*   pos = (const int*)  d_in[1];
    const float* WQ  = (const float*)d_in[2];
    const float* WK  = (const float*)d_in[3];
    const float* WV  = (const float*)d_in[4];
    const float* WO  = (const float*)d_in[5];
    float* out = (float*)d_out;

    __half* xh;
    cudaGetSymbolAddress((void**)&xh, g_xh);

    tohalf_kernel<<<(M * D / 4 + 255) / 256, 256>>>(x, xh, M * D / 4);
    tohalfW_kernel<<<dim3(D * D / 4 / 256, 4, 1), 256>>>(WQ, WK, WV, WO);

    cudaFuncSetAttribute(qkv_kernel,
                         cudaFuncAttributeMaxDynamicSharedMemorySize,
                         GEMM_SMEM_BYTES);
    cudaFuncSetAttribute(oproj_kernel,
                         cudaFuncAttributeMaxDynamicSharedMemorySize,
                         GEMM_SMEM_BYTES);
    cudaFuncSetAttribute(attn_kernel,
                         cudaFuncAttributeMaxDynamicSharedMemorySize,
                         ATT_SMEM_BYTES);

    qkv_kernel<<<dim3(D / 128, M / 128, 3), 256, GEMM_SMEM_BYTES>>>(pos);
    attn_kernel<<<dim3(S / 128, NH, B), 256, ATT_SMEM_BYTES>>>();
    oproj_kernel<<<dim3(D / 128, M / 128, 1), 256, GEMM_SMEM_BYTES>>>(out);
}